// round 4
// baseline (speedup 1.0000x reference)
#include <cuda_runtime.h>
#include <cstdint>

// Problem constants (fixed by the reference)
#define NN    4096     // nodes
#define INF_  128      // input features
#define OUTF  32       // output features per head
#define NH    4        // heads
#define NC    128      // NH*OUTF = output channels

// Tiling for the attention kernel
#define ITILE  64                 // i-rows per block
#define JSTEP  16                 // j's staged per round
#define JSPLIT 8                  // j-range splits (partial softmax, additive)
#define JCHUNK (NN / JSPLIT)      // 512 j's per block
#define WPAD   260                // padded per-jj slab stride (floats): 4h*64i=256 -> 260

// ---------------- scratch (device globals; no allocation allowed) ----------------
__device__ __align__(16) float g_Wx[NN * NC];            // 2 MB  : x @ W
__device__ __align__(16) float g_es[NN * NH];            // e_src[n,h]
__device__ __align__(16) float g_ed[NN * NH];            // e_dst[n,h]
__device__ __align__(16) float g_nump[JSPLIT][NN * NC];  // 16 MB : partial numerators
__device__ __align__(16) float g_Zp[JSPLIT][NN * NH];    // partial denominators

// ---------------- f32x2 packed-FMA helpers (Blackwell FFMA2) ----------------
__device__ __forceinline__ unsigned long long pk2(float lo, float hi) {
    unsigned long long r;
    asm("mov.b64 %0, {%1, %2};" : "=l"(r) : "f"(lo), "f"(hi));
    return r;
}
__device__ __forceinline__ void fma2(unsigned long long& d,
                                     unsigned long long a,
                                     unsigned long long b) {
    asm("fma.rn.f32x2 %0, %1, %2, %0;" : "+l"(d) : "l"(a), "l"(b));
}
__device__ __forceinline__ void upk2(unsigned long long v, float& lo, float& hi) {
    asm("mov.b64 {%0, %1}, %2;" : "=f"(lo), "=f"(hi) : "l"(v));
}

// =====================================================================
// K1: Wx = x @ W  (4096x128 @ 128x128), plus per-row e_src/e_dst.
// Block = 128 threads handles 16 rows. W staged in 64-row k-chunks.
// Thread (cg=t&31, rg=t>>5) owns cols c0..c0+3 (c0=4*cg) x rows rg*4..rg*4+3.
// =====================================================================
__global__ __launch_bounds__(128) void k_gemm(const float* __restrict__ x,
                                              const float* __restrict__ W,
                                              const float* __restrict__ a) {
    __shared__ __align__(16) float Ws[64 * 128];   // 32 KB  (k-chunk of W)
    __shared__ __align__(16) float xs[16 * 128];   //  8 KB  (x row tile)
    const int t = threadIdx.x;
    const int rowbase = blockIdx.x * 16;

    // load x tile (16 rows)
    #pragma unroll
    for (int p = 0; p < 4; p++) {
        int idx4 = t + 128 * p;                 // 0..511 float4's
        int r  = idx4 >> 5;
        int c4 = (idx4 & 31) << 2;
        *(float4*)&xs[r * 128 + c4] =
            *(const float4*)&x[(size_t)(rowbase + r) * INF_ + c4];
    }

    const int cg = t & 31;
    const int rg = t >> 5;
    const int c0 = cg << 2;

    float acc[4][4];
    #pragma unroll
    for (int i = 0; i < 4; i++)
        #pragma unroll
        for (int j = 0; j < 4; j++) acc[i][j] = 0.f;

    for (int kc = 0; kc < INF_; kc += 64) {
        __syncthreads();
        // load W chunk rows kc..kc+63
        #pragma unroll
        for (int p = 0; p < 16; p++) {
            int idx4 = t + 128 * p;             // 0..2047 float4's
            int kr = idx4 >> 5;
            int c4 = (idx4 & 31) << 2;
            *(float4*)&Ws[kr * 128 + c4] =
                *(const float4*)&W[(size_t)(kc + kr) * NC + c4];
        }
        __syncthreads();
        #pragma unroll 8
        for (int k = 0; k < 64; k++) {
            float4 w4 = *(const float4*)&Ws[k * 128 + c0];
            #pragma unroll
            for (int rr = 0; rr < 4; rr++) {
                float xv = xs[(rg * 4 + rr) * 128 + kc + k];
                acc[rr][0] += xv * w4.x;
                acc[rr][1] += xv * w4.y;
                acc[rr][2] += xv * w4.z;
                acc[rr][3] += xv * w4.w;
            }
        }
    }

    // write Wx; reduce e_src/e_dst within 8-lane head groups
    const int h = cg >> 3;             // head of this column group
    const int fbase = c0 & 31;         // f of first owned column
    #pragma unroll
    for (int rr = 0; rr < 4; rr++) {
        int row = rowbase + rg * 4 + rr;
        *(float4*)&g_Wx[(size_t)row * NC + c0] =
            make_float4(acc[rr][0], acc[rr][1], acc[rr][2], acc[rr][3]);
        float es = 0.f, ed = 0.f;
        #pragma unroll
        for (int q = 0; q < 4; q++) {
            float av = __ldg(&a[h * (2 * OUTF) + fbase + q]);          // a_src
            float bv = __ldg(&a[h * (2 * OUTF) + OUTF + fbase + q]);   // a_dst
            es += acc[rr][q] * av;
            ed += acc[rr][q] * bv;
        }
        es += __shfl_xor_sync(0xffffffffu, es, 1);
        es += __shfl_xor_sync(0xffffffffu, es, 2);
        es += __shfl_xor_sync(0xffffffffu, es, 4);
        ed += __shfl_xor_sync(0xffffffffu, ed, 1);
        ed += __shfl_xor_sync(0xffffffffu, ed, 2);
        ed += __shfl_xor_sync(0xffffffffu, ed, 4);
        if ((cg & 7) == 0) {
            g_es[row * NH + h] = es;
            g_ed[row * NH + h] = ed;
        }
    }
}

// =====================================================================
// K2: attention aggregation (partial over a j-chunk, no max needed).
// Grid: (JSPLIT, NN/ITILE). Block 256 threads.
//
// Staging role  : thread (s_i=t>>2, s_q=t&3) owns i = ibase+s_i and j's
//                 {q*4..q*4+3} of each 16-j round; loads adj as int4,
//                 computes w = mask * exp(leaky(es+ed)), stores to wS,
//                 and accumulates Z[i,h] locally.
// FMA role      : warp owns head h=warp&3; lane owns 8 i's (ig=hi2+lane>>3)
//                 and 4 f's (f0=(lane&7)*4). 16 FFMA2 + 3 LDS per j.
// =====================================================================
__global__ __launch_bounds__(256) void k_attn(const int* __restrict__ adj) {
    __shared__ __align__(16) float wS[JSTEP * WPAD];   // 16.25 KB : w[jj][h][i]
    __shared__ __align__(16) float wxS[JSTEP * NC];    //  8 KB    : Wx rows

    const int t = threadIdx.x;
    const int ibase = blockIdx.y * ITILE;
    const int jc = blockIdx.x;
    const int jbase = jc * JCHUNK;

    // ---- staging role params ----
    const int s_i = t >> 2;
    const int s_q = t & 3;
    const int gi = ibase + s_i;
    const float4 es4 = *(const float4*)&g_es[gi * NH];
    const int* adj_row = adj + (size_t)gi * NN + jbase + (s_q << 2);
    float z0 = 0.f, z1 = 0.f, z2 = 0.f, z3 = 0.f;

    // ---- FMA role params ----
    const int warp = t >> 5, lane = t & 31;
    const int h = warp & 3;
    const int ig = ((warp >> 2) << 2) + (lane >> 3);
    const int f0 = (lane & 7) << 2;
    const int i0 = ig << 3;
    const int wx_off = h * OUTF + f0;
    const int w_off = h * ITILE + i0;

    unsigned long long acc[8][2];
    #pragma unroll
    for (int k = 0; k < 8; k++) { acc[k][0] = 0ull; acc[k][1] = 0ull; }

    // ---- Wx staging role params ----
    const int wx_jj = t >> 4;
    const int wx_c = (t & 15) << 3;

    for (int jr = 0; jr < JCHUNK; jr += JSTEP) {
        const int j0 = jbase + jr;

        // stage Wx rows j0..j0+15 (8 floats per thread)
        {
            const float4* src =
                (const float4*)&g_Wx[(size_t)(j0 + wx_jj) * NC + wx_c];
            float4 v0 = src[0];
            float4 v1 = src[1];
            *(float4*)&wxS[wx_jj * NC + wx_c] = v0;
            *(float4*)&wxS[wx_jj * NC + wx_c + 4] = v1;
        }

        // stage w for (i = s_i, 4 j's, all 4 heads); accumulate Z locally
        {
            const int4 am = *(const int4*)(adj_row + jr);
            #pragma unroll
            for (int m = 0; m < 4; m++) {
                int jj = (s_q << 2) + m;
                int av = (m == 0) ? am.x : (m == 1) ? am.y : (m == 2) ? am.z : am.w;
                float4 ed4 = *(const float4*)&g_ed[(size_t)(j0 + jj) * NH];
                float w0 = 0.f, w1 = 0.f, w2 = 0.f, w3 = 0.f;
                if (av) {
                    float s;
                    s = es4.x + ed4.x; s = fmaxf(s, 0.2f * s); w0 = __expf(s);
                    s = es4.y + ed4.y; s = fmaxf(s, 0.2f * s); w1 = __expf(s);
                    s = es4.z + ed4.z; s = fmaxf(s, 0.2f * s); w2 = __expf(s);
                    s = es4.w + ed4.w; s = fmaxf(s, 0.2f * s); w3 = __expf(s);
                }
                z0 += w0; z1 += w1; z2 += w2; z3 += w3;
                float* dst = &wS[jj * WPAD + s_i];
                dst[0]   = w0;
                dst[64]  = w1;
                dst[128] = w2;
                dst[192] = w3;
            }
        }
        __syncthreads();

        // FMA loop: out[i,h,f] += w[i,j,h] * Wx[j,h,f]
        #pragma unroll
        for (int jj = 0; jj < JSTEP; jj++) {
            float4 wx = *(const float4*)&wxS[jj * NC + wx_off];
            unsigned long long wx01 = pk2(wx.x, wx.y);
            unsigned long long wx23 = pk2(wx.z, wx.w);
            const float* wp = &wS[jj * WPAD + w_off];
            float4 wa = *(const float4*)wp;
            float4 wb = *(const float4*)(wp + 4);
            unsigned long long wd;
            wd = pk2(wa.x, wa.x); fma2(acc[0][0], wd, wx01); fma2(acc[0][1], wd, wx23);
            wd = pk2(wa.y, wa.y); fma2(acc[1][0], wd, wx01); fma2(acc[1][1], wd, wx23);
            wd = pk2(wa.z, wa.z); fma2(acc[2][0], wd, wx01); fma2(acc[2][1], wd, wx23);
            wd = pk2(wa.w, wa.w); fma2(acc[3][0], wd, wx01); fma2(acc[3][1], wd, wx23);
            wd = pk2(wb.x, wb.x); fma2(acc[4][0], wd, wx01); fma2(acc[4][1], wd, wx23);
            wd = pk2(wb.y, wb.y); fma2(acc[5][0], wd, wx01); fma2(acc[5][1], wd, wx23);
            wd = pk2(wb.z, wb.z); fma2(acc[6][0], wd, wx01); fma2(acc[6][1], wd, wx23);
            wd = pk2(wb.w, wb.w); fma2(acc[7][0], wd, wx01); fma2(acc[7][1], wd, wx23);
        }
        __syncthreads();
    }

    // write partial numerators (each (jc, i, c) written exactly once)
    float* nump = g_nump[jc];
    #pragma unroll
    for (int k = 0; k < 8; k++) {
        float o0, o1, o2, o3;
        upk2(acc[k][0], o0, o1);
        upk2(acc[k][1], o2, o3);
        *(float4*)&nump[(size_t)(ibase + i0 + k) * NC + wx_off] =
            make_float4(o0, o1, o2, o3);
    }

    // reduce Z across the 4 s_q threads sharing an i (lanes xor 1, xor 2)
    z0 += __shfl_xor_sync(0xffffffffu, z0, 1);
    z0 += __shfl_xor_sync(0xffffffffu, z0, 2);
    z1 += __shfl_xor_sync(0xffffffffu, z1, 1);
    z1 += __shfl_xor_sync(0xffffffffu, z1, 2);
    z2 += __shfl_xor_sync(0xffffffffu, z2, 1);
    z2 += __shfl_xor_sync(0xffffffffu, z2, 2);
    z3 += __shfl_xor_sync(0xffffffffu, z3, 1);
    z3 += __shfl_xor_sync(0xffffffffu, z3, 2);
    if (s_q == 0) {
        *(float4*)&g_Zp[jc][gi * NH] = make_float4(z0, z1, z2, z3);
    }
}

// =====================================================================
// K3: normalize — out = (sum_s num_s) / (sum_s Z_s). Every output written.
// =====================================================================
__global__ __launch_bounds__(256) void k_norm(float* __restrict__ out) {
    int g = blockIdx.x * 256 + threadIdx.x;   // over N*NC/4 float4's
    int i = g >> 5;
    int c4 = (g & 31) << 2;
    int h = c4 >> 5;
    float4 num = make_float4(0.f, 0.f, 0.f, 0.f);
    float Z = 0.f;
    #pragma unroll
    for (int s = 0; s < JSPLIT; s++) {
        float4 v = *(const float4*)&g_nump[s][(size_t)i * NC + c4];
        num.x += v.x; num.y += v.y; num.z += v.z; num.w += v.w;
        Z += g_Zp[s][i * NH + h];
    }
    float inv = 1.f / Z;
    *(float4*)&out[(size_t)i * NC + c4] =
        make_float4(num.x * inv, num.y * inv, num.z * inv, num.w * inv);
}

// =====================================================================
extern "C" void kernel_launch(void* const* d_in, const int* in_sizes, int n_in,
                              void* d_out, int out_size) {
    const float* x = nullptr;
    const int*   adj = nullptr;
    const float* W = nullptr;
    const float* a = nullptr;
    for (int i = 0; i < n_in; i++) {
        switch (in_sizes[i]) {
            case NN * INF_:       x   = (const float*)d_in[i]; break; // 524288
            case NN * NN:         adj = (const int*)d_in[i];   break; // 16777216
            case INF_ * NC:       W   = (const float*)d_in[i]; break; // 16384
            case NH * 2 * OUTF:   a   = (const float*)d_in[i]; break; // 256
            default: break;
        }
    }
    float* out = (float*)d_out;

    k_gemm<<<NN / 16, 128>>>(x, W, a);
    dim3 g_attn(JSPLIT, NN / ITILE);
    k_attn<<<g_attn, 256>>>(adj);
    k_norm<<<(NN * NC / 4) / 256, 256>>>(out);
    (void)out_size;
}

// round 6
// speedup vs baseline: 1.0303x; 1.0303x over previous
#include <cuda_runtime.h>
#include <cstdint>

// Problem constants (fixed by the reference)
#define NN    4096     // nodes
#define INF_  128      // input features
#define OUTF  32       // output features per head
#define NH    4        // heads
#define NC    128      // NH*OUTF = output channels

// Tiling for the attention kernel
#define ITILE  64                 // i-rows per block
#define JSTEP  16                 // j's staged per round
#define JSPLIT 8                  // j-range splits (partial softmax, additive)
#define JCHUNK (NN / JSPLIT)      // 512 j's per block
#define NROUND (JCHUNK / JSTEP)   // 32 rounds
#define WPAD   256                // per-jj slab stride (floats): 4h * 64i

#define SMEM_ATTN ((2 * JSTEP * WPAD + 2 * JSTEP * NC) * sizeof(float))  // 49152 dyn

// ---------------- scratch (device globals; no allocation allowed) ----------------
__device__ __align__(16) float g_Wx[NN * NC];            // 2 MB  : x @ W
__device__ __align__(16) float g_es[NN * NH];            // e_src[n,h]
__device__ __align__(16) float g_ed[NN * NH];            // e_dst[n,h]
__device__ __align__(16) float g_nump[JSPLIT][NN * NC];  // 16 MB : partial numerators
__device__ __align__(16) float g_Zp[JSPLIT][NN * NH];    // partial denominators

// ---------------- f32x2 packed-FMA helpers (Blackwell FFMA2) ----------------
__device__ __forceinline__ unsigned long long pk2(float lo, float hi) {
    unsigned long long r;
    asm("mov.b64 %0, {%1, %2};" : "=l"(r) : "f"(lo), "f"(hi));
    return r;
}
__device__ __forceinline__ void fma2(unsigned long long& d,
                                     unsigned long long a,
                                     unsigned long long b) {
    asm("fma.rn.f32x2 %0, %1, %2, %0;" : "+l"(d) : "l"(a), "l"(b));
}
__device__ __forceinline__ void upk2(unsigned long long v, float& lo, float& hi) {
    asm("mov.b64 {%0, %1}, %2;" : "=f"(lo), "=f"(hi) : "l"(v));
}

__device__ __forceinline__ int adj_elem(const int4& a, const int4& b, int jq) {
    switch (jq) {
        case 0: return a.x; case 1: return a.y; case 2: return a.z; case 3: return a.w;
        case 4: return b.x; case 5: return b.y; case 6: return b.z; default: return b.w;
    }
}

// Compute w = mask * exp(leaky(es+ed)) for 8 j's x 4 heads; store into wS slab;
// accumulate partial softmax denominators in z.
__device__ __forceinline__ void stage_w(float* __restrict__ wSn,
                                        const float4* __restrict__ edsrc,
                                        int4 p0, int4 p1, float4 es4,
                                        int s_i, int s_q, float4& z) {
    float* dbase = wSn + s_i;
    #pragma unroll
    for (int jq = 0; jq < 8; jq++) {
        int jj = (s_q << 3) + jq;
        int av = adj_elem(p0, p1, jq);
        float4 e4 = edsrc[jj];
        float s0 = es4.x + e4.x; s0 = fmaxf(s0, 0.2f * s0);
        float s1 = es4.y + e4.y; s1 = fmaxf(s1, 0.2f * s1);
        float s2 = es4.z + e4.z; s2 = fmaxf(s2, 0.2f * s2);
        float s3 = es4.w + e4.w; s3 = fmaxf(s3, 0.2f * s3);
        float w0 = av ? __expf(s0) : 0.f;
        float w1 = av ? __expf(s1) : 0.f;
        float w2 = av ? __expf(s2) : 0.f;
        float w3 = av ? __expf(s3) : 0.f;
        z.x += w0; z.y += w1; z.z += w2; z.w += w3;
        float* d = dbase + jj * WPAD;
        d[0]   = w0;      // h=0
        d[64]  = w1;      // h=1
        d[128] = w2;      // h=2
        d[192] = w3;      // h=3
    }
}

// =====================================================================
// K1: Wx = x @ W  (4096x128 @ 128x128), plus per-row e_src/e_dst.
// Block = 256 threads handles 16 rows.
// =====================================================================
__global__ __launch_bounds__(256) void k_gemm(const float* __restrict__ x,
                                              const float* __restrict__ W,
                                              const float* __restrict__ a) {
    __shared__ __align__(16) float Ws[64 * 128];   // 32 KB  (k-chunk of W)
    __shared__ __align__(16) float xs[16 * 128];   //  8 KB  (x row tile)
    const int t = threadIdx.x;
    const int rowbase = blockIdx.x * 16;

    #pragma unroll
    for (int p = 0; p < 2; p++) {
        int idx4 = t + 256 * p;
        int r  = idx4 >> 5;
        int c4 = (idx4 & 31) << 2;
        *(float4*)&xs[r * 128 + c4] =
            *(const float4*)&x[(size_t)(rowbase + r) * INF_ + c4];
    }

    const int cg = t & 31;
    const int rg = t >> 5;     // 0..7
    const int c0 = cg << 2;

    float acc[2][4];
    #pragma unroll
    for (int i = 0; i < 2; i++)
        #pragma unroll
        for (int j = 0; j < 4; j++) acc[i][j] = 0.f;

    for (int kc = 0; kc < INF_; kc += 64) {
        __syncthreads();
        #pragma unroll
        for (int p = 0; p < 8; p++) {
            int idx4 = t + 256 * p;
            int kr = idx4 >> 5;
            int c4 = (idx4 & 31) << 2;
            *(float4*)&Ws[kr * 128 + c4] =
                *(const float4*)&W[(size_t)(kc + kr) * NC + c4];
        }
        __syncthreads();
        #pragma unroll 8
        for (int k = 0; k < 64; k++) {
            float4 w4 = *(const float4*)&Ws[k * 128 + c0];
            #pragma unroll
            for (int rr = 0; rr < 2; rr++) {
                float xv = xs[(rg * 2 + rr) * 128 + kc + k];
                acc[rr][0] += xv * w4.x;
                acc[rr][1] += xv * w4.y;
                acc[rr][2] += xv * w4.z;
                acc[rr][3] += xv * w4.w;
            }
        }
    }

    const int h = cg >> 3;
    const int fbase = c0 & 31;
    #pragma unroll
    for (int rr = 0; rr < 2; rr++) {
        int row = rowbase + rg * 2 + rr;
        *(float4*)&g_Wx[(size_t)row * NC + c0] =
            make_float4(acc[rr][0], acc[rr][1], acc[rr][2], acc[rr][3]);
        float es = 0.f, ed = 0.f;
        #pragma unroll
        for (int q = 0; q < 4; q++) {
            float av = __ldg(&a[h * (2 * OUTF) + fbase + q]);
            float bv = __ldg(&a[h * (2 * OUTF) + OUTF + fbase + q]);
            es += acc[rr][q] * av;
            ed += acc[rr][q] * bv;
        }
        es += __shfl_xor_sync(0xffffffffu, es, 1);
        es += __shfl_xor_sync(0xffffffffu, es, 2);
        es += __shfl_xor_sync(0xffffffffu, es, 4);
        ed += __shfl_xor_sync(0xffffffffu, ed, 1);
        ed += __shfl_xor_sync(0xffffffffu, ed, 2);
        ed += __shfl_xor_sync(0xffffffffu, ed, 4);
        if ((cg & 7) == 0) {
            g_es[row * NH + h] = es;
            g_ed[row * NH + h] = ed;
        }
    }
}

// =====================================================================
// K2: attention aggregation, double-buffered + software pipelined.
// Grid: (JSPLIT, NN/ITILE). Block 128 threads = 4 warps (warp == head).
//
// FMA role : warp h; lane (ig=lane>>2, fg=lane&3) owns i0=ig*8 (8 i's)
//            and f0=fg*8 (8 f's). Per jj: 4 LDS.128 + 32 FFMA2, w-pairs
//            come directly from ulonglong2 loads (no packing movs).
// Staging  : thread (s_i=t>>1, s_q=t&1) owns row i=ibase+s_i, 8 j's,
//            all 4 heads; adj/Wx prefetched one round ahead of use;
//            ed rows two rounds ahead via a tiny smem pipeline.
// NOTE: total smem = 49152 dyn + 512 static > 48 KB -> needs the
//       MaxDynamicSharedMemorySize opt-in set in kernel_launch.
// =====================================================================
__global__ __launch_bounds__(128, 3) void k_attn(const int* __restrict__ adj) {
    extern __shared__ __align__(16) float dyns[];
    float* wSbuf  = dyns;                        // [2][16][256]  32 KB
    float* wxSbuf = dyns + 2 * JSTEP * WPAD;     // [2][16][128]  16 KB
    __shared__ __align__(16) float4 edS_s[2][JSTEP];  // ed pipeline (512 B)

    const int t = threadIdx.x;
    const int ibase = blockIdx.y * ITILE;
    const int jc = blockIdx.x;
    const int jbase = jc * JCHUNK;

    // ---- staging role params ----
    const int s_i = t >> 1;
    const int s_q = t & 1;
    const int gi = ibase + s_i;
    const float4 es4 = *(const float4*)&g_es[(size_t)gi * NH];
    const int4* ap = (const int4*)(adj + (size_t)gi * NN + jbase);
    float4 z = make_float4(0.f, 0.f, 0.f, 0.f);

    // ---- FMA role params ----
    const int h = t >> 5;            // warp == head
    const int lane = t & 31;
    const int ig = lane >> 2;        // 0..7 : i0 = ig*8
    const int fg = lane & 3;         // 0..3 : f0 = fg*8
    const int wread_off = h * 64 + (ig << 3);
    const int xread_off = h * 32 + (fg << 3);

    unsigned long long acc[4][8];
    #pragma unroll
    for (int ip = 0; ip < 4; ip++)
        #pragma unroll
        for (int k = 0; k < 8; k++) acc[ip][k] = 0ull;

    // ================= prologue: stage round 0 into buffer 0 =================
    {
        const float4* wsrc = (const float4*)&g_Wx[(size_t)jbase * NC];
        float4* wdst = (float4*)wxSbuf;
        #pragma unroll
        for (int p = 0; p < 4; p++) wdst[t + 128 * p] = wsrc[t + 128 * p];

        int4 q0 = ap[s_q * 2];
        int4 q1 = ap[s_q * 2 + 1];
        stage_w(wSbuf, (const float4*)&g_ed[(size_t)jbase * NH],
                q0, q1, es4, s_i, s_q, z);

        if (t < JSTEP) {
            edS_s[1][t] = *(const float4*)&g_ed[(size_t)(jbase + JSTEP + t) * NH];
        }
    }
    __syncthreads();

    // ================= main loop =================
    for (int r = 0; r < NROUND; r++) {
        const int b = r & 1;
        const float* wSb  = wSbuf  + b * (JSTEP * WPAD);
        const float* wxSb = wxSbuf + b * (JSTEP * NC);
        float* wSn  = wSbuf  + (b ^ 1) * (JSTEP * WPAD);
        float* wxSn = wxSbuf + (b ^ 1) * (JSTEP * NC);

        // ---- EARLY: issue loads for round r+1 / r+2 (latency hidden by FMA) ----
        int4 p0, p1;
        float4 wx4[4];
        if (r < NROUND - 1) {
            int base4 = (r + 1) * 4 + s_q * 2;
            p0 = ap[base4];
            p1 = ap[base4 + 1];
            const float4* wsrc =
                (const float4*)&g_Wx[(size_t)(jbase + (r + 1) * JSTEP) * NC];
            #pragma unroll
            for (int p = 0; p < 4; p++) wx4[p] = wsrc[t + 128 * p];
        }
        if (r < NROUND - 2 && t < JSTEP) {
            edS_s[b][t] =
                *(const float4*)&g_ed[(size_t)(jbase + (r + 2) * JSTEP + t) * NH];
        }

        // ---- FMA over buffer b ----
        #pragma unroll 4
        for (int jj = 0; jj < JSTEP; jj++) {
            const float* wp = wSb + jj * WPAD + wread_off;
            ulonglong2 wA = *(const ulonglong2*)wp;        // (w0,w1),(w2,w3)
            ulonglong2 wB = *(const ulonglong2*)(wp + 4);  // (w4,w5),(w6,w7)
            const float* xp = wxSb + jj * NC + xread_off;
            float4 x0 = *(const float4*)xp;
            float4 x1 = *(const float4*)(xp + 4);
            unsigned long long xd[8];
            xd[0] = pk2(x0.x, x0.x); xd[1] = pk2(x0.y, x0.y);
            xd[2] = pk2(x0.z, x0.z); xd[3] = pk2(x0.w, x0.w);
            xd[4] = pk2(x1.x, x1.x); xd[5] = pk2(x1.y, x1.y);
            xd[6] = pk2(x1.z, x1.z); xd[7] = pk2(x1.w, x1.w);
            #pragma unroll
            for (int k = 0; k < 8; k++) {
                fma2(acc[0][k], wA.x, xd[k]);
                fma2(acc[1][k], wA.y, xd[k]);
                fma2(acc[2][k], wB.x, xd[k]);
                fma2(acc[3][k], wB.y, xd[k]);
            }
        }

        // ---- CONSUME: stage round r+1 into buffer b^1 ----
        if (r < NROUND - 1) {
            float4* wdst = (float4*)wxSn;
            #pragma unroll
            for (int p = 0; p < 4; p++) wdst[t + 128 * p] = wx4[p];
            stage_w(wSn, (const float4*)&edS_s[b ^ 1][0],
                    p0, p1, es4, s_i, s_q, z);
        }
        __syncthreads();
    }

    // ================= epilogue =================
    float* nump = g_nump[jc];
    const int i0 = ig << 3;
    const int cbase = h * 32 + (fg << 3);
    #pragma unroll
    for (int ip = 0; ip < 4; ip++) {
        float lo[8], hi[8];
        #pragma unroll
        for (int k = 0; k < 8; k++) upk2(acc[ip][k], lo[k], hi[k]);
        size_t r0 = (size_t)(ibase + i0 + 2 * ip) * NC + cbase;
        *(float4*)&nump[r0]          = make_float4(lo[0], lo[1], lo[2], lo[3]);
        *(float4*)&nump[r0 + 4]      = make_float4(lo[4], lo[5], lo[6], lo[7]);
        *(float4*)&nump[r0 + NC]     = make_float4(hi[0], hi[1], hi[2], hi[3]);
        *(float4*)&nump[r0 + NC + 4] = make_float4(hi[4], hi[5], hi[6], hi[7]);
    }

    z.x += __shfl_xor_sync(0xffffffffu, z.x, 1);
    z.y += __shfl_xor_sync(0xffffffffu, z.y, 1);
    z.z += __shfl_xor_sync(0xffffffffu, z.z, 1);
    z.w += __shfl_xor_sync(0xffffffffu, z.w, 1);
    if (s_q == 0) {
        *(float4*)&g_Zp[jc][(size_t)gi * NH] = z;
    }
}

// =====================================================================
// K3: normalize — out = (sum_s num_s) / (sum_s Z_s). Every output written.
// =====================================================================
__global__ __launch_bounds__(256) void k_norm(float* __restrict__ out) {
    int g = blockIdx.x * 256 + threadIdx.x;   // over N*NC/4 float4's
    int i = g >> 5;
    int c4 = (g & 31) << 2;
    int h = c4 >> 5;
    float4 num = make_float4(0.f, 0.f, 0.f, 0.f);
    float Z = 0.f;
    #pragma unroll
    for (int s = 0; s < JSPLIT; s++) {
        float4 v = *(const float4*)&g_nump[s][(size_t)i * NC + c4];
        num.x += v.x; num.y += v.y; num.z += v.z; num.w += v.w;
        Z += g_Zp[s][i * NH + h];
    }
    float inv = 1.f / Z;
    *(float4*)&out[(size_t)i * NC + c4] =
        make_float4(num.x * inv, num.y * inv, num.z * inv, num.w * inv);
}

// =====================================================================
extern "C" void kernel_launch(void* const* d_in, const int* in_sizes, int n_in,
                              void* d_out, int out_size) {
    const float* x = nullptr;
    const int*   adj = nullptr;
    const float* W = nullptr;
    const float* a = nullptr;
    for (int i = 0; i < n_in; i++) {
        switch (in_sizes[i]) {
            case NN * INF_:       x   = (const float*)d_in[i]; break; // 524288
            case NN * NN:         adj = (const int*)d_in[i];   break; // 16777216
            case INF_ * NC:       W   = (const float*)d_in[i]; break; // 16384
            case NH * 2 * OUTF:   a   = (const float*)d_in[i]; break; // 256
            default: break;
        }
    }
    float* out = (float*)d_out;

    // Opt-in for >48KB total smem on k_attn (host-side attribute, not a
    // stream op; idempotent and deterministic — safe under graph capture).
    cudaFuncSetAttribute(k_attn, cudaFuncAttributeMaxDynamicSharedMemorySize,
                         (int)SMEM_ATTN + 1024);

    k_gemm<<<NN / 16, 256>>>(x, W, a);
    dim3 g_attn(JSPLIT, NN / ITILE);
    k_attn<<<g_attn, 128, SMEM_ATTN>>>(adj);
    k_norm<<<(NN * NC / 4) / 256, 256>>>(out);
    (void)out_size;
}

// round 8
// speedup vs baseline: 1.6555x; 1.6068x over previous
#include <cuda_runtime.h>
#include <cstdint>

// Problem constants (fixed by the reference)
#define NN    4096     // nodes
#define INF_  128      // input features
#define OUTF  32       // output features per head
#define NH    4        // heads
#define NC    128      // NH*OUTF

// Attention tiling
#define ITILE  128                // i-rows per block
#define JSPLIT 8                  // j-range splits (additive partial softmax)
#define JCHUNK (NN / JSPLIT)      // 512
#define JSTEP  32                 // j's per round
#define NROUND (JCHUNK / JSTEP)   // 16

#define LOG2E 1.4426950408889634f
#define WXS_STRIDE 136            // 128 + 8 pad: B-frag reads bank-conflict-free

// ---------------- scratch (device globals; no allocation allowed) ----------------
__device__ __align__(16) float g_Wx[NN * NC];            // 2 MB
__device__ __align__(16) float g_es[NN * NH];            // e_src * log2e
__device__ __align__(16) float g_ed[NN * NH];            // e_dst * log2e
__device__ __align__(16) float g_nump[JSPLIT][NN * NC];  // 16 MB partial numerators
__device__ __align__(16) float g_Zp[JSPLIT][NN * NH];    // partial denominators

// ---------------- helpers ----------------
__device__ __forceinline__ uint32_t cvt_tf32(float v) {
    uint32_t r;
    asm("cvt.rna.tf32.f32 %0, %1;" : "=r"(r) : "f"(v));
    return r;
}
// P = mask * 2^(leaky(s)); s already in log2 domain
__device__ __forceinline__ float pval(float s, uint32_t bit) {
    float lk = fmaxf(s, 0.2f * s);
    float e;
    asm("ex2.approx.f32 %0, %1;" : "=f"(e) : "f"(lk));
    return bit ? e : 0.0f;
}
// m16n8k8 tf32 HMMA (sm_80+ baseline PTX; works on plain sm_100)
__device__ __forceinline__ void mma8(float* d, uint32_t a0, uint32_t a1,
                                     uint32_t a2, uint32_t a3,
                                     uint32_t b0, uint32_t b1) {
    asm volatile(
        "mma.sync.aligned.m16n8k8.row.col.f32.tf32.tf32.f32 "
        "{%0,%1,%2,%3}, {%4,%5,%6,%7}, {%8,%9}, {%0,%1,%2,%3};"
        : "+f"(d[0]), "+f"(d[1]), "+f"(d[2]), "+f"(d[3])
        : "r"(a0), "r"(a1), "r"(a2), "r"(a3), "r"(b0), "r"(b1));
}

// =====================================================================
// K1: Wx = x @ W (full W staged once, single sync), plus e_src/e_dst
// (pre-scaled by log2e). Dynamic smem 72 KB -> needs opt-in attribute.
// =====================================================================
__global__ __launch_bounds__(256) void k_gemm(const float* __restrict__ x,
                                              const float* __restrict__ W,
                                              const float* __restrict__ a) {
    extern __shared__ __align__(16) float sm[];
    float* Ws = sm;            // 128*128 floats = 64 KB
    float* xs = sm + 16384;    // 16*128  floats =  8 KB
    const int t = threadIdx.x;
    const int rowbase = blockIdx.x * 16;

    #pragma unroll
    for (int p = 0; p < 16; p++) {
        int idx = t + 256 * p;
        int kr = idx >> 5, c4 = (idx & 31) << 2;
        *(float4*)&Ws[kr * 128 + c4] = *(const float4*)&W[(size_t)kr * NC + c4];
    }
    #pragma unroll
    for (int p = 0; p < 2; p++) {
        int idx = t + 256 * p;
        int r = idx >> 5, c4 = (idx & 31) << 2;
        *(float4*)&xs[r * 128 + c4] =
            *(const float4*)&x[(size_t)(rowbase + r) * INF_ + c4];
    }
    __syncthreads();

    const int cg = t & 31;
    const int rg = t >> 5;
    const int c0 = cg << 2;

    float acc[2][4];
    #pragma unroll
    for (int i = 0; i < 2; i++)
        #pragma unroll
        for (int j = 0; j < 4; j++) acc[i][j] = 0.f;

    #pragma unroll 8
    for (int k = 0; k < INF_; k++) {
        float4 w4 = *(const float4*)&Ws[k * 128 + c0];
        #pragma unroll
        for (int rr = 0; rr < 2; rr++) {
            float xv = xs[(rg * 2 + rr) * 128 + k];
            acc[rr][0] += xv * w4.x;
            acc[rr][1] += xv * w4.y;
            acc[rr][2] += xv * w4.z;
            acc[rr][3] += xv * w4.w;
        }
    }

    const int h = cg >> 3;
    const int fbase = c0 & 31;
    #pragma unroll
    for (int rr = 0; rr < 2; rr++) {
        int row = rowbase + rg * 2 + rr;
        *(float4*)&g_Wx[(size_t)row * NC + c0] =
            make_float4(acc[rr][0], acc[rr][1], acc[rr][2], acc[rr][3]);
        float es = 0.f, ed = 0.f;
        #pragma unroll
        for (int q = 0; q < 4; q++) {
            float av = __ldg(&a[h * (2 * OUTF) + fbase + q]);
            float bv = __ldg(&a[h * (2 * OUTF) + OUTF + fbase + q]);
            es += acc[rr][q] * av;
            ed += acc[rr][q] * bv;
        }
        es += __shfl_xor_sync(0xffffffffu, es, 1);
        es += __shfl_xor_sync(0xffffffffu, es, 2);
        es += __shfl_xor_sync(0xffffffffu, es, 4);
        ed += __shfl_xor_sync(0xffffffffu, ed, 1);
        ed += __shfl_xor_sync(0xffffffffu, ed, 2);
        ed += __shfl_xor_sync(0xffffffffu, ed, 4);
        if ((cg & 7) == 0) {
            g_es[row * NH + h] = es * LOG2E;   // log2 domain (leaky is scale-inv)
            g_ed[row * NH + h] = ed * LOG2E;
        }
    }
}

// =====================================================================
// K2: HMMA (mma.sync tf32) attention aggregation.
// Grid (JSPLIT, NN/ITILE) = (8, 32). Block 256 = 8 warps.
// Warp w: head h = w&3, i-half = w>>2 -> 64i x 32f output over K=512.
// Per round (32 j): adj ballot-packed into adjW[128] bitmask words +
// Wx^T tf32-staged into SMEM (stride 136, conflict-free B reads); then
// 4 k-steps, each: A fragments (P values) built in registers (one exp
// per P element chip-wide), 4x4 m16n8k8 HMMA. Z accumulated from the
// tf32-rounded P for softmax consistency.
// =====================================================================
__global__ __launch_bounds__(256) void k_attn(const int* __restrict__ adj) {
    __shared__ __align__(16) uint32_t WxS[JSTEP * WXS_STRIDE];  // 17408 B
    __shared__ __align__(16) float edS[JCHUNK * NH];            //  8192 B
    __shared__ uint32_t adjW[ITILE];                            //   512 B

    const int t = threadIdx.x;
    const int w = t >> 5, lane = t & 31;
    const int g = lane >> 2, tig = lane & 3;
    const int h = w & 3, ihalf = w >> 2;
    const int ibase = blockIdx.y * ITILE;
    const int jc = blockIdx.x;
    const int jbase = jc * JCHUNK;
    const int gib = ibase + ihalf * 64;

    // stage ed chunk once (512 x 4 floats)
    for (int idx = t; idx < JCHUNK; idx += 256)
        *(float4*)&edS[idx * 4] = *(const float4*)&g_ed[(size_t)(jbase + idx) * NH];

    // es for my 8 rows (log2 domain)
    float es_[4][2];
    #pragma unroll
    for (int mt = 0; mt < 4; mt++) {
        es_[mt][0] = g_es[(size_t)(gib + mt * 16 + g) * NH + h];
        es_[mt][1] = g_es[(size_t)(gib + mt * 16 + g + 8) * NH + h];
    }

    float acc[4][4][4];
    #pragma unroll
    for (int mt = 0; mt < 4; mt++)
        #pragma unroll
        for (int nt = 0; nt < 4; nt++)
            #pragma unroll
            for (int q = 0; q < 4; q++) acc[mt][nt][q] = 0.f;
    float z[4][2];
    #pragma unroll
    for (int mt = 0; mt < 4; mt++) { z[mt][0] = 0.f; z[mt][1] = 0.f; }

    // adj staging rows for this warp: w*16 .. w*16+15
    const int* arow = adj + (size_t)(ibase + w * 16) * NN + jbase;

    for (int r = 0; r < NROUND; r++) {
        // ---- issue all staging LDGs (MLP), then ballots/stores ----
        int av[16];
        #pragma unroll
        for (int q = 0; q < 16; q++)
            av[q] = arow[(size_t)q * NN + r * JSTEP + lane];
        float4 wv[4];
        #pragma unroll
        for (int p = 0; p < 4; p++) {
            int idx = t + 256 * p;
            int j = idx >> 5, c4 = (idx & 31) << 2;
            wv[p] = *(const float4*)&g_Wx[(size_t)(jbase + r * JSTEP + j) * NC + c4];
        }
        #pragma unroll
        for (int q = 0; q < 16; q++) {
            uint32_t m = __ballot_sync(0xffffffffu, av[q] != 0);
            if (lane == 0) adjW[w * 16 + q] = m;
        }
        #pragma unroll
        for (int p = 0; p < 4; p++) {
            int idx = t + 256 * p;
            int j = idx >> 5, c4 = (idx & 31) << 2;
            uint32_t* d = &WxS[j * WXS_STRIDE + c4];
            d[0] = cvt_tf32(wv[p].x);
            d[1] = cvt_tf32(wv[p].y);
            d[2] = cvt_tf32(wv[p].z);
            d[3] = cvt_tf32(wv[p].w);
        }
        __syncthreads();

        // my 8 mask words for this round
        uint32_t aw[4][2];
        #pragma unroll
        for (int mt = 0; mt < 4; mt++) {
            aw[mt][0] = adjW[ihalf * 64 + mt * 16 + g];
            aw[mt][1] = adjW[ihalf * 64 + mt * 16 + g + 8];
        }

        #pragma unroll
        for (int ks = 0; ks < 4; ks++) {
            // B fragments (4 n-tiles), conflict-free (banks 8*tig+g)
            uint32_t b0[4], b1[4];
            #pragma unroll
            for (int nt = 0; nt < 4; nt++) {
                b0[nt] = WxS[(ks * 8 + tig) * WXS_STRIDE + h * OUTF + nt * 8 + g];
                b1[nt] = WxS[(ks * 8 + tig + 4) * WXS_STRIDE + h * OUTF + nt * 8 + g];
            }
            float ed0 = edS[(r * JSTEP + ks * 8 + tig) * NH + h];
            float ed1 = edS[(r * JSTEP + ks * 8 + tig + 4) * NH + h];
            const int j0 = ks * 8 + tig, j1 = j0 + 4;

            #pragma unroll
            for (int mt = 0; mt < 4; mt++) {
                float p0 = pval(es_[mt][0] + ed0, (aw[mt][0] >> j0) & 1u);
                float p1 = pval(es_[mt][1] + ed0, (aw[mt][1] >> j0) & 1u);
                float p2 = pval(es_[mt][0] + ed1, (aw[mt][0] >> j1) & 1u);
                float p3 = pval(es_[mt][1] + ed1, (aw[mt][1] >> j1) & 1u);
                uint32_t a0 = cvt_tf32(p0), a1 = cvt_tf32(p1);
                uint32_t a2 = cvt_tf32(p2), a3 = cvt_tf32(p3);
                z[mt][0] += __uint_as_float(a0) + __uint_as_float(a2);
                z[mt][1] += __uint_as_float(a1) + __uint_as_float(a3);
                #pragma unroll
                for (int nt = 0; nt < 4; nt++)
                    mma8(acc[mt][nt], a0, a1, a2, a3, b0[nt], b1[nt]);
            }
        }
        __syncthreads();
    }

    // ---- epilogue: D fragments -> partial numerators; Z reduce ----
    float* np = g_nump[jc];
    #pragma unroll
    for (int mt = 0; mt < 4; mt++) {
        int r0 = gib + mt * 16 + g;
        #pragma unroll
        for (int nt = 0; nt < 4; nt++) {
            int c = h * OUTF + nt * 8 + tig * 2;
            *(float2*)&np[(size_t)r0 * NC + c] =
                make_float2(acc[mt][nt][0], acc[mt][nt][1]);
            *(float2*)&np[(size_t)(r0 + 8) * NC + c] =
                make_float2(acc[mt][nt][2], acc[mt][nt][3]);
        }
        float z0 = z[mt][0], z1 = z[mt][1];
        z0 += __shfl_xor_sync(0xffffffffu, z0, 1);
        z0 += __shfl_xor_sync(0xffffffffu, z0, 2);
        z1 += __shfl_xor_sync(0xffffffffu, z1, 1);
        z1 += __shfl_xor_sync(0xffffffffu, z1, 2);
        if (tig == 0) {
            g_Zp[jc][(size_t)r0 * NH + h] = z0;
            g_Zp[jc][(size_t)(r0 + 8) * NH + h] = z1;
        }
    }
}

// =====================================================================
// K3: normalize — out = (sum_s num_s) / (sum_s Z_s).
// =====================================================================
__global__ __launch_bounds__(256) void k_norm(float* __restrict__ out) {
    int g = blockIdx.x * 256 + threadIdx.x;
    int i = g >> 5;
    int c4 = (g & 31) << 2;
    int h = c4 >> 5;
    float4 num = make_float4(0.f, 0.f, 0.f, 0.f);
    float Z = 0.f;
    #pragma unroll
    for (int s = 0; s < JSPLIT; s++) {
        float4 v = *(const float4*)&g_nump[s][(size_t)i * NC + c4];
        num.x += v.x; num.y += v.y; num.z += v.z; num.w += v.w;
        Z += g_Zp[s][i * NH + h];
    }
    float inv = 1.f / Z;
    *(float4*)&out[(size_t)i * NC + c4] =
        make_float4(num.x * inv, num.y * inv, num.z * inv, num.w * inv);
}

// =====================================================================
extern "C" void kernel_launch(void* const* d_in, const int* in_sizes, int n_in,
                              void* d_out, int out_size) {
    const float* x = nullptr;
    const int*   adj = nullptr;
    const float* W = nullptr;
    const float* a = nullptr;
    for (int i = 0; i < n_in; i++) {
        switch (in_sizes[i]) {
            case NN * INF_:       x   = (const float*)d_in[i]; break;
            case NN * NN:         adj = (const int*)d_in[i];   break;
            case INF_ * NC:       W   = (const float*)d_in[i]; break;
            case NH * 2 * OUTF:   a   = (const float*)d_in[i]; break;
            default: break;
        }
    }
    float* out = (float*)d_out;

    // k_gemm uses 72 KB dynamic smem: opt-in (host attribute; graph-safe).
    const int gemm_smem = (16384 + 2048) * (int)sizeof(float);  // 73728
    cudaFuncSetAttribute(k_gemm, cudaFuncAttributeMaxDynamicSharedMemorySize,
                         gemm_smem);

    k_gemm<<<NN / 16, 256, gemm_smem>>>(x, W, a);
    dim3 g_attn(JSPLIT, NN / ITILE);   // (8, 32)
    k_attn<<<g_attn, 256>>>(adj);
    k_norm<<<(NN * NC / 4) / 256, 256>>>(out);
    (void)out_size;
}

// round 9
// speedup vs baseline: 1.7475x; 1.0556x over previous
#include <cuda_runtime.h>
#include <cstdint>

// Problem constants (fixed by the reference)
#define NN    4096     // nodes
#define INF_  128      // input features
#define OUTF  32       // output features per head
#define NH    4        // heads
#define NC    128      // NH*OUTF

// Attention tiling
#define ITILE  64                 // i-rows per block
#define JSPLIT 8                  // j-range splits (additive partial softmax)
#define JCHUNK (NN / JSPLIT)      // 512
#define JSTEP  32                 // j's per round
#define NROUND (JCHUNK / JSTEP)   // 16

#define LOG2E 1.4426950408889634f
#define WXS_STRIDE 136            // 128 + 8 pad: B-frag reads bank-conflict-free

// ---------------- scratch (device globals; no allocation allowed) ----------------
__device__ __align__(16) float g_Wx[NN * NC];            // 2 MB
__device__ __align__(16) float g_es[NN * NH];            // e_src * log2e
__device__ __align__(16) float g_ed[NN * NH];            // e_dst * log2e
__device__ __align__(16) float g_nump[JSPLIT][NN * NC];  // 16 MB partial numerators
__device__ __align__(16) float g_Zp[JSPLIT][NN * NH];    // partial denominators

// ---------------- helpers ----------------
__device__ __forceinline__ uint32_t cvt_tf32(float v) {
    uint32_t r;
    asm("cvt.rna.tf32.f32 %0, %1;" : "=r"(r) : "f"(v));
    return r;
}
// P = mask * 2^(leaky(s)); s already in log2 domain
__device__ __forceinline__ float pval(float s, uint32_t bit) {
    float lk = fmaxf(s, 0.2f * s);
    float e;
    asm("ex2.approx.f32 %0, %1;" : "=f"(e) : "f"(lk));
    return bit ? e : 0.0f;
}
// m16n8k8 tf32 HMMA (sm_80+ baseline PTX; works on plain sm_100)
__device__ __forceinline__ void mma8(float* d, uint32_t a0, uint32_t a1,
                                     uint32_t a2, uint32_t a3,
                                     uint32_t b0, uint32_t b1) {
    asm volatile(
        "mma.sync.aligned.m16n8k8.row.col.f32.tf32.tf32.f32 "
        "{%0,%1,%2,%3}, {%4,%5,%6,%7}, {%8,%9}, {%0,%1,%2,%3};"
        : "+f"(d[0]), "+f"(d[1]), "+f"(d[2]), "+f"(d[3])
        : "r"(a0), "r"(a1), "r"(a2), "r"(a3), "r"(b0), "r"(b1));
}
__device__ __forceinline__ int ldcs_i(const int* p) {
    int v;
    asm volatile("ld.global.cs.s32 %0, [%1];" : "=r"(v) : "l"(p));
    return v;
}

// =====================================================================
// K1: Wx = x @ W (full W staged once, single sync), plus e_src/e_dst
// (pre-scaled by log2e). Dynamic smem 72 KB -> opt-in attribute.
// =====================================================================
__global__ __launch_bounds__(256) void k_gemm(const float* __restrict__ x,
                                              const float* __restrict__ W,
                                              const float* __restrict__ a) {
    extern __shared__ __align__(16) float sm[];
    float* Ws = sm;            // 128*128 floats = 64 KB
    float* xs = sm + 16384;    // 16*128  floats =  8 KB
    const int t = threadIdx.x;
    const int rowbase = blockIdx.x * 16;

    #pragma unroll
    for (int p = 0; p < 16; p++) {
        int idx = t + 256 * p;
        int kr = idx >> 5, c4 = (idx & 31) << 2;
        *(float4*)&Ws[kr * 128 + c4] = *(const float4*)&W[(size_t)kr * NC + c4];
    }
    #pragma unroll
    for (int p = 0; p < 2; p++) {
        int idx = t + 256 * p;
        int r = idx >> 5, c4 = (idx & 31) << 2;
        *(float4*)&xs[r * 128 + c4] =
            *(const float4*)&x[(size_t)(rowbase + r) * INF_ + c4];
    }
    __syncthreads();

    const int cg = t & 31;
    const int rg = t >> 5;
    const int c0 = cg << 2;

    float acc[2][4];
    #pragma unroll
    for (int i = 0; i < 2; i++)
        #pragma unroll
        for (int j = 0; j < 4; j++) acc[i][j] = 0.f;

    #pragma unroll 8
    for (int k = 0; k < INF_; k++) {
        float4 w4 = *(const float4*)&Ws[k * 128 + c0];
        #pragma unroll
        for (int rr = 0; rr < 2; rr++) {
            float xv = xs[(rg * 2 + rr) * 128 + k];
            acc[rr][0] += xv * w4.x;
            acc[rr][1] += xv * w4.y;
            acc[rr][2] += xv * w4.z;
            acc[rr][3] += xv * w4.w;
        }
    }

    const int h = cg >> 3;
    const int fbase = c0 & 31;
    #pragma unroll
    for (int rr = 0; rr < 2; rr++) {
        int row = rowbase + rg * 2 + rr;
        *(float4*)&g_Wx[(size_t)row * NC + c0] =
            make_float4(acc[rr][0], acc[rr][1], acc[rr][2], acc[rr][3]);
        float es = 0.f, ed = 0.f;
        #pragma unroll
        for (int q = 0; q < 4; q++) {
            float av = __ldg(&a[h * (2 * OUTF) + fbase + q]);
            float bv = __ldg(&a[h * (2 * OUTF) + OUTF + fbase + q]);
            es += acc[rr][q] * av;
            ed += acc[rr][q] * bv;
        }
        es += __shfl_xor_sync(0xffffffffu, es, 1);
        es += __shfl_xor_sync(0xffffffffu, es, 2);
        es += __shfl_xor_sync(0xffffffffu, es, 4);
        ed += __shfl_xor_sync(0xffffffffu, ed, 1);
        ed += __shfl_xor_sync(0xffffffffu, ed, 2);
        ed += __shfl_xor_sync(0xffffffffu, ed, 4);
        if ((cg & 7) == 0) {
            g_es[row * NH + h] = es * LOG2E;   // log2 domain (leaky is scale-inv)
            g_ed[row * NH + h] = ed * LOG2E;
        }
    }
}

// =====================================================================
// K2: HMMA tf32 attention aggregation, software-pipelined.
// Grid (JSPLIT, NN/ITILE) = (8, 64). Block 128 = 4 warps; warp == head.
// Each warp: 64i x 32f output over K=512, as 4x4 m16n8k8 tiles x 4 ks.
// Pipeline: adj for round r+1 prefetched into registers at round top,
// ballot-packed into adjW[b^1] AFTER the MMA loop; Wx^T restaged from
// L2-hot g_Wx after compute; one __syncthreads per round.
// =====================================================================
__global__ __launch_bounds__(128, 4) void k_attn(const int* __restrict__ adj) {
    __shared__ __align__(16) uint32_t WxS[2][JSTEP * WXS_STRIDE];  // 34816 B
    __shared__ __align__(16) float edS[JCHUNK * NH];               //  8192 B
    __shared__ uint32_t adjW[2][ITILE];                            //   512 B

    const int t = threadIdx.x;
    const int w = t >> 5, lane = t & 31;
    const int g = lane >> 2, tig = lane & 3;
    const int h = w;                    // warp == head
    const int ibase = blockIdx.y * ITILE;
    const int jc = blockIdx.x;
    const int jbase = jc * JCHUNK;

    // stage ed chunk once (512 x 4 floats, 4 float4 per thread)
    for (int idx = t; idx < JCHUNK; idx += 128)
        *(float4*)&edS[idx * 4] = *(const float4*)&g_ed[(size_t)(jbase + idx) * NH];

    // es for my 8 rows (log2 domain)
    float es_[4][2];
    #pragma unroll
    for (int mt = 0; mt < 4; mt++) {
        es_[mt][0] = g_es[(size_t)(ibase + mt * 16 + g) * NH + h];
        es_[mt][1] = g_es[(size_t)(ibase + mt * 16 + g + 8) * NH + h];
    }

    float acc[4][4][4];
    #pragma unroll
    for (int mt = 0; mt < 4; mt++)
        #pragma unroll
        for (int nt = 0; nt < 4; nt++)
            #pragma unroll
            for (int q = 0; q < 4; q++) acc[mt][nt][q] = 0.f;
    float z[4][2];
    #pragma unroll
    for (int mt = 0; mt < 4; mt++) { z[mt][0] = 0.f; z[mt][1] = 0.f; }

    // adj staging rows for this warp: ibase + w*16 .. +15 (lane = j)
    const int* arow = adj + (size_t)(ibase + w * 16) * NN + jbase;

    // ---------------- prologue: stage round 0 ----------------
    {
        int av[16];
        #pragma unroll
        for (int q = 0; q < 16; q++) av[q] = ldcs_i(&arow[(size_t)q * NN + lane]);
        #pragma unroll
        for (int q = 0; q < 16; q++) {
            uint32_t m = __ballot_sync(0xffffffffu, av[q] != 0);
            if (lane == 0) adjW[0][w * 16 + q] = m;
        }
        #pragma unroll
        for (int p = 0; p < 8; p++) {
            int idx = t + 128 * p;
            int j = idx >> 5, c4 = (idx & 31) << 2;
            float4 v = *(const float4*)&g_Wx[(size_t)(jbase + j) * NC + c4];
            uint32_t* d = &WxS[0][j * WXS_STRIDE + c4];
            d[0] = cvt_tf32(v.x); d[1] = cvt_tf32(v.y);
            d[2] = cvt_tf32(v.z); d[3] = cvt_tf32(v.w);
        }
    }
    __syncthreads();

    // ---------------- main loop ----------------
    for (int r = 0; r < NROUND; r++) {
        const int b = r & 1;

        // EARLY: prefetch next round's adj (consumed after the MMA loop)
        int avn[16];
        if (r < NROUND - 1) {
            #pragma unroll
            for (int q = 0; q < 16; q++)
                avn[q] = ldcs_i(&arow[(size_t)q * NN + (r + 1) * JSTEP + lane]);
        }

        // my 8 mask words for this round
        uint32_t aw[4][2];
        #pragma unroll
        for (int mt = 0; mt < 4; mt++) {
            aw[mt][0] = adjW[b][mt * 16 + g];
            aw[mt][1] = adjW[b][mt * 16 + g + 8];
        }

        #pragma unroll
        for (int ks = 0; ks < 4; ks++) {
            // B fragments (4 n-tiles), conflict-free (banks 8*tig+g)
            uint32_t b0[4], b1[4];
            #pragma unroll
            for (int nt = 0; nt < 4; nt++) {
                b0[nt] = WxS[b][(ks * 8 + tig) * WXS_STRIDE + h * OUTF + nt * 8 + g];
                b1[nt] = WxS[b][(ks * 8 + tig + 4) * WXS_STRIDE + h * OUTF + nt * 8 + g];
            }
            float ed0 = edS[(r * JSTEP + ks * 8 + tig) * NH + h];
            float ed1 = edS[(r * JSTEP + ks * 8 + tig + 4) * NH + h];
            const int j0 = ks * 8 + tig, j1 = j0 + 4;

            #pragma unroll
            for (int mt = 0; mt < 4; mt++) {
                float p0 = pval(es_[mt][0] + ed0, (aw[mt][0] >> j0) & 1u);
                float p1 = pval(es_[mt][1] + ed0, (aw[mt][1] >> j0) & 1u);
                float p2 = pval(es_[mt][0] + ed1, (aw[mt][0] >> j1) & 1u);
                float p3 = pval(es_[mt][1] + ed1, (aw[mt][1] >> j1) & 1u);
                uint32_t a0 = cvt_tf32(p0), a1 = cvt_tf32(p1);
                uint32_t a2 = cvt_tf32(p2), a3 = cvt_tf32(p3);
                z[mt][0] += __uint_as_float(a0) + __uint_as_float(a2);
                z[mt][1] += __uint_as_float(a1) + __uint_as_float(a3);
                #pragma unroll
                for (int nt = 0; nt < 4; nt++)
                    mma8(acc[mt][nt], a0, a1, a2, a3, b0[nt], b1[nt]);
            }
        }

        // LATE: pack prefetched adj + restage Wx^T into buffer b^1
        if (r < NROUND - 1) {
            #pragma unroll
            for (int q = 0; q < 16; q++) {
                uint32_t m = __ballot_sync(0xffffffffu, avn[q] != 0);
                if (lane == 0) adjW[b ^ 1][w * 16 + q] = m;
            }
            #pragma unroll
            for (int p = 0; p < 8; p++) {
                int idx = t + 128 * p;
                int j = idx >> 5, c4 = (idx & 31) << 2;
                float4 v = *(const float4*)
                    &g_Wx[(size_t)(jbase + (r + 1) * JSTEP + j) * NC + c4];
                uint32_t* d = &WxS[b ^ 1][j * WXS_STRIDE + c4];
                d[0] = cvt_tf32(v.x); d[1] = cvt_tf32(v.y);
                d[2] = cvt_tf32(v.z); d[3] = cvt_tf32(v.w);
            }
        }
        __syncthreads();
    }

    // ---- epilogue: D fragments -> partial numerators; Z reduce ----
    float* np = g_nump[jc];
    #pragma unroll
    for (int mt = 0; mt < 4; mt++) {
        int r0 = ibase + mt * 16 + g;
        #pragma unroll
        for (int nt = 0; nt < 4; nt++) {
            int c = h * OUTF + nt * 8 + tig * 2;
            *(float2*)&np[(size_t)r0 * NC + c] =
                make_float2(acc[mt][nt][0], acc[mt][nt][1]);
            *(float2*)&np[(size_t)(r0 + 8) * NC + c] =
                make_float2(acc[mt][nt][2], acc[mt][nt][3]);
        }
        float z0 = z[mt][0], z1 = z[mt][1];
        z0 += __shfl_xor_sync(0xffffffffu, z0, 1);
        z0 += __shfl_xor_sync(0xffffffffu, z0, 2);
        z1 += __shfl_xor_sync(0xffffffffu, z1, 1);
        z1 += __shfl_xor_sync(0xffffffffu, z1, 2);
        if (tig == 0) {
            g_Zp[jc][(size_t)r0 * NH + h] = z0;
            g_Zp[jc][(size_t)(r0 + 8) * NH + h] = z1;
        }
    }
}

// =====================================================================
// K3: normalize — out = (sum_s num_s) / (sum_s Z_s).
// =====================================================================
__global__ __launch_bounds__(256) void k_norm(float* __restrict__ out) {
    int g = blockIdx.x * 256 + threadIdx.x;
    int i = g >> 5;
    int c4 = (g & 31) << 2;
    int h = c4 >> 5;
    float4 num = make_float4(0.f, 0.f, 0.f, 0.f);
    float Z = 0.f;
    #pragma unroll
    for (int s = 0; s < JSPLIT; s++) {
        float4 v = *(const float4*)&g_nump[s][(size_t)i * NC + c4];
        num.x += v.x; num.y += v.y; num.z += v.z; num.w += v.w;
        Z += g_Zp[s][i * NH + h];
    }
    float inv = 1.f / Z;
    *(float4*)&out[(size_t)i * NC + c4] =
        make_float4(num.x * inv, num.y * inv, num.z * inv, num.w * inv);
}

// =====================================================================
extern "C" void kernel_launch(void* const* d_in, const int* in_sizes, int n_in,
                              void* d_out, int out_size) {
    const float* x = nullptr;
    const int*   adj = nullptr;
    const float* W = nullptr;
    const float* a = nullptr;
    for (int i = 0; i < n_in; i++) {
        switch (in_sizes[i]) {
            case NN * INF_:       x   = (const float*)d_in[i]; break;
            case NN * NN:         adj = (const int*)d_in[i];   break;
            case INF_ * NC:       W   = (const float*)d_in[i]; break;
            case NH * 2 * OUTF:   a   = (const float*)d_in[i]; break;
            default: break;
        }
    }
    float* out = (float*)d_out;

    // k_gemm uses 72 KB dynamic smem: opt-in (host attribute; graph-safe).
    const int gemm_smem = (16384 + 2048) * (int)sizeof(float);  // 73728
    cudaFuncSetAttribute(k_gemm, cudaFuncAttributeMaxDynamicSharedMemorySize,
                         gemm_smem);

    k_gemm<<<NN / 16, 256, gemm_smem>>>(x, W, a);
    dim3 g_attn(JSPLIT, NN / ITILE);   // (8, 64)
    k_attn<<<g_attn, 128>>>(adj);
    k_norm<<<(NN * NC / 4) / 256, 256>>>(out);
    (void)out_size;
}